// round 1
// baseline (speedup 1.0000x reference)
#include <cuda_runtime.h>
#include <math.h>

// ---------------------------------------------------------------------------
// Shapes (fixed per reference):
//   x  : (256,128,128) fp32            (4,194,304 elems)
//   w1,w2,w3 : (128,256,3,3), b*: (128)
//   w4 : (256,128), b4: (256)
//   p1 = conv1(x)          -> flat (128,16384) == Q (16384,128) row-major
//   p2 = conv2(x[::2,::2]) -> flat (128,4096)  == K' (128,4096) row-major
//   p3 = conv3(x[::2,::2]) -> flat (128,4096)  == V (4096,128) row-major
//   attn = softmax(Q @ K' / 128); p123 = attn @ V   (flash-fused, 16384x128)
//   p4 = relu(p123 @ w4^T + b4) -> M = p4.reshape + x ; out = (M, x)
// ---------------------------------------------------------------------------

#define HP 128
#define WP 128
#define S1 16384
#define S2 4096
#define NXE 4194304      // 256*128*128

// Scratch (device globals — no allocation allowed)
__device__ float g_p1[128 * S1];   // conv1 out, [co][s]  (== Q row-major)
__device__ float g_p2[128 * S2];   // conv2 out, [co][s]  (== K' row-major)
__device__ float g_p3[128 * S2];   // conv3 out, [co][s]  (== V row-major)
__device__ float g_po[S1 * 128];   // attention output p123 (16384 x 128)

// ---------------------------------------------------------------------------
// Direct 3x3 conv + ReLU.  Block: 256 threads = 8 co-groups(x4 co) x 32 pixel
// segments (8 rows x 4 col-segs of 8).  Tile: 32 co x (8 x 32) pixels.
// Input chunked over ci in groups of 8 through shared memory.
// STRIDE=2 implements x[:, ::2, ::2] on the fly (logical HL x HL grid).
// ---------------------------------------------------------------------------
#define CIT 8
#define COT 32

template <int HL, int STRIDE>
__device__ __forceinline__ void conv_body(
    const float* __restrict__ x, const float* __restrict__ w,
    const float* __restrict__ bias, float* __restrict__ out,
    int h0, int w0, int co0)
{
    __shared__ float sin_[CIT][10][34];
    __shared__ float sw_[CIT][9][COT];

    const int tid = threadIdx.x;
    const int cog = tid >> 5;          // 0..7 -> co = co0 + cog*4 + q
    const int seg = tid & 31;          // 0..31
    const int row = seg >> 2;          // 0..7
    const int cb  = (seg & 3) << 3;    // 0,8,16,24

    float acc[4][8];
#pragma unroll
    for (int q = 0; q < 4; q++)
#pragma unroll
        for (int p = 0; p < 8; p++) acc[q][p] = 0.f;

    for (int cib = 0; cib < 256; cib += CIT) {
        __syncthreads();
        // input chunk: CIT x 10 x 34 (halo of 1, SAME padding)
        for (int idx = tid; idx < CIT * 10 * 34; idx += 256) {
            int ci  = idx / 340;
            int rem = idx - ci * 340;
            int r   = rem / 34;
            int c   = rem - r * 34;
            int gh  = h0 + r - 1;
            int gw  = w0 + c - 1;
            float v = 0.f;
            if ((unsigned)gh < (unsigned)HL && (unsigned)gw < (unsigned)HL)
                v = x[(cib + ci) * (HP * WP) + (gh * STRIDE) * WP + gw * STRIDE];
            sin_[ci][r][c] = v;
        }
        // weights: sw[ci][tap][co]
        for (int idx = tid; idx < CIT * 9 * COT; idx += 256) {
            int co  = idx & (COT - 1);
            int t2  = idx >> 5;
            int tap = t2 % 9;
            int ci  = t2 / 9;
            sw_[ci][tap][co] = w[(co0 + co) * (256 * 9) + (cib + ci) * 9 + tap];
        }
        __syncthreads();

#pragma unroll 1
        for (int ci = 0; ci < CIT; ci++) {
            float4 wv[9];
#pragma unroll
            for (int t = 0; t < 9; t++)
                wv[t] = *(const float4*)&sw_[ci][t][cog * 4];
            float xin[3][10];
#pragma unroll
            for (int dy = 0; dy < 3; dy++)
#pragma unroll
                for (int c = 0; c < 10; c++)
                    xin[dy][c] = sin_[ci][row + dy][cb + c];
#pragma unroll
            for (int p = 0; p < 8; p++) {
#pragma unroll
                for (int dy = 0; dy < 3; dy++) {
#pragma unroll
                    for (int dx = 0; dx < 3; dx++) {
                        float  v  = xin[dy][p + dx];
                        float4 ww = wv[dy * 3 + dx];
                        acc[0][p] += ww.x * v;
                        acc[1][p] += ww.y * v;
                        acc[2][p] += ww.z * v;
                        acc[3][p] += ww.w * v;
                    }
                }
            }
        }
    }

#pragma unroll
    for (int q = 0; q < 4; q++) {
        int   co = co0 + cog * 4 + q;
        float bb = bias[co];
#pragma unroll
        for (int p = 0; p < 8; p++) {
            float v = acc[q][p] + bb;
            out[co * (HL * HL) + (h0 + row) * HL + (w0 + cb + p)] = fmaxf(v, 0.f);
        }
    }
}

__global__ __launch_bounds__(256, 2)
void k_conv1(const float* __restrict__ x, const float* __restrict__ w1,
             const float* __restrict__ b1)
{
    conv_body<128, 1>(x, w1, b1, g_p1,
                      blockIdx.y * 8, blockIdx.x * 32, blockIdx.z * COT);
}

// conv2 + conv3 fused in one launch (same downsampled input tiles); z selects.
__global__ __launch_bounds__(256, 2)
void k_conv23(const float* __restrict__ x,
              const float* __restrict__ w2, const float* __restrict__ b2,
              const float* __restrict__ w3, const float* __restrict__ b3)
{
    int z   = blockIdx.z;
    int ws  = z >> 2;
    int co0 = (z & 3) * COT;
    const float* w  = ws ? w3 : w2;
    const float* bb = ws ? b3 : b2;
    float*       o  = ws ? g_p3 : g_p2;
    conv_body<64, 2>(x, w, bb, o, blockIdx.y * 8, blockIdx.x * 32, co0);
}

// ---------------------------------------------------------------------------
// Flash attention: Q (16384x128) @ K'(128x4096), online softmax, @ V(4096x128)
// Block: 256 threads (tx 0..15, ty 0..15). BM=64 rows/block, k-tiles of 64.
// S fragment per thread: 4x4.  O fragment: 4 rows x 8 cols.
// ---------------------------------------------------------------------------
__global__ __launch_bounds__(256)
void k_flash()
{
    extern __shared__ float sm[];
    float* Qst = sm;                    // [128][68]  Q transposed, padded
    float* Ks  = Qst + 128 * 68;        // [128][64]  K' tile
    float* Vs  = Ks + 128 * 64;         // [64][128]  V tile
    float* Ps  = Vs + 64 * 128;         // [64][64]   P tile (row-major)

    const int tid  = threadIdx.x;
    const int tx   = tid & 15;
    const int ty   = tid >> 4;
    const int row0 = blockIdx.x * 64;

    // load Q block transposed (once)
    for (int idx = tid; idx < 64 * 128; idx += 256) {
        int i = idx >> 7;
        int j = idx & 127;
        Qst[j * 68 + i] = g_p1[(row0 + i) * 128 + j];
    }

    float o[4][8];
    float m[4], l[4];
#pragma unroll
    for (int r = 0; r < 4; r++) {
        m[r] = -1e30f;
        l[r] = 0.f;
#pragma unroll
        for (int n = 0; n < 8; n++) o[r][n] = 0.f;
    }
    const float invtau = 1.0f / 128.0f;

    for (int kb = 0; kb < S2; kb += 64) {
        __syncthreads();   // previous GEMM2 done with Ks/Vs/Ps
        // K' tile: rows j=0..127, cols kb..kb+63
        for (int idx = tid; idx < 128 * 16; idx += 256) {
            int j  = idx >> 4;
            int c4 = idx & 15;
            *(float4*)&Ks[j * 64 + c4 * 4] =
                *(const float4*)&g_p2[j * S2 + kb + c4 * 4];
        }
        // V tile: rows kb..kb+63, 128 cols each — contiguous block
        for (int idx = tid; idx < 64 * 32; idx += 256) {
            *(float4*)&Vs[idx * 4] = *(const float4*)&g_p3[kb * 128 + idx * 4];
        }
        __syncthreads();

        // GEMM1: S = Q @ K'
        float s[4][4];
#pragma unroll
        for (int r = 0; r < 4; r++)
#pragma unroll
            for (int c = 0; c < 4; c++) s[r][c] = 0.f;
#pragma unroll 4
        for (int j = 0; j < 128; j++) {
            float4 a = *(const float4*)&Qst[j * 68 + ty * 4];
            float4 b = *(const float4*)&Ks[j * 64 + tx * 4];
            s[0][0] += a.x * b.x; s[0][1] += a.x * b.y; s[0][2] += a.x * b.z; s[0][3] += a.x * b.w;
            s[1][0] += a.y * b.x; s[1][1] += a.y * b.y; s[1][2] += a.y * b.z; s[1][3] += a.y * b.w;
            s[2][0] += a.z * b.x; s[2][1] += a.z * b.y; s[2][2] += a.z * b.z; s[2][3] += a.z * b.w;
            s[3][0] += a.w * b.x; s[3][1] += a.w * b.y; s[3][2] += a.w * b.z; s[3][3] += a.w * b.w;
        }

        // online softmax (rows span 16 tx lanes within half-warp; xor 8/4/2/1)
#pragma unroll
        for (int r = 0; r < 4; r++) {
            float t = fmaxf(fmaxf(s[r][0], s[r][1]), fmaxf(s[r][2], s[r][3]));
            t = fmaxf(t, __shfl_xor_sync(0xffffffffu, t, 8));
            t = fmaxf(t, __shfl_xor_sync(0xffffffffu, t, 4));
            t = fmaxf(t, __shfl_xor_sync(0xffffffffu, t, 2));
            t = fmaxf(t, __shfl_xor_sync(0xffffffffu, t, 1));
            float mn    = fmaxf(m[r], t);
            float alpha = __expf((m[r] - mn) * invtau);
            m[r] = mn;
            float4 p;
            p.x = __expf((s[r][0] - mn) * invtau);
            p.y = __expf((s[r][1] - mn) * invtau);
            p.z = __expf((s[r][2] - mn) * invtau);
            p.w = __expf((s[r][3] - mn) * invtau);
            l[r] = l[r] * alpha + (p.x + p.y + p.z + p.w);
            *(float4*)&Ps[(ty * 4 + r) * 64 + tx * 4] = p;
#pragma unroll
            for (int n = 0; n < 8; n++) o[r][n] *= alpha;
        }
        __syncthreads();

        // GEMM2: O += P @ V
#pragma unroll 2
        for (int k = 0; k < 64; k++) {
            float  a0 = Ps[(ty * 4 + 0) * 64 + k];
            float  a1 = Ps[(ty * 4 + 1) * 64 + k];
            float  a2 = Ps[(ty * 4 + 2) * 64 + k];
            float  a3 = Ps[(ty * 4 + 3) * 64 + k];
            float4 b0 = *(const float4*)&Vs[k * 128 + tx * 8];
            float4 b1 = *(const float4*)&Vs[k * 128 + tx * 8 + 4];
            o[0][0] += a0 * b0.x; o[0][1] += a0 * b0.y; o[0][2] += a0 * b0.z; o[0][3] += a0 * b0.w;
            o[0][4] += a0 * b1.x; o[0][5] += a0 * b1.y; o[0][6] += a0 * b1.z; o[0][7] += a0 * b1.w;
            o[1][0] += a1 * b0.x; o[1][1] += a1 * b0.y; o[1][2] += a1 * b0.z; o[1][3] += a1 * b0.w;
            o[1][4] += a1 * b1.x; o[1][5] += a1 * b1.y; o[1][6] += a1 * b1.z; o[1][7] += a1 * b1.w;
            o[2][0] += a2 * b0.x; o[2][1] += a2 * b0.y; o[2][2] += a2 * b0.z; o[2][3] += a2 * b0.w;
            o[2][4] += a2 * b1.x; o[2][5] += a2 * b1.y; o[2][6] += a2 * b1.z; o[2][7] += a2 * b1.w;
            o[3][0] += a3 * b0.x; o[3][1] += a3 * b0.y; o[3][2] += a3 * b0.z; o[3][3] += a3 * b0.w;
            o[3][4] += a3 * b1.x; o[3][5] += a3 * b1.y; o[3][6] += a3 * b1.z; o[3][7] += a3 * b1.w;
        }
    }

    // finalize: reduce l over tx group, normalize, write
#pragma unroll
    for (int r = 0; r < 4; r++) {
        float ll = l[r];
        ll += __shfl_xor_sync(0xffffffffu, ll, 8);
        ll += __shfl_xor_sync(0xffffffffu, ll, 4);
        ll += __shfl_xor_sync(0xffffffffu, ll, 2);
        ll += __shfl_xor_sync(0xffffffffu, ll, 1);
        float inv  = 1.0f / ll;
        int   grow = row0 + ty * 4 + r;
        float4 v0  = make_float4(o[r][0] * inv, o[r][1] * inv, o[r][2] * inv, o[r][3] * inv);
        float4 v1  = make_float4(o[r][4] * inv, o[r][5] * inv, o[r][6] * inv, o[r][7] * inv);
        *(float4*)&g_po[grow * 128 + tx * 8]     = v0;
        *(float4*)&g_po[grow * 128 + tx * 8 + 4] = v1;
    }
}

// ---------------------------------------------------------------------------
// Linear + ReLU + residual + tuple write.
// p4[r][o] = relu(sum_c p123[r][c]*w4[o][c] + b4[o]);
// out[t] = p4_flat[t] + x[t];  out[NXE + t] = x[t]   (t = r*256 + o)
// ---------------------------------------------------------------------------
__global__ __launch_bounds__(256)
void k_linear(const float* __restrict__ w4, const float* __restrict__ b4,
              const float* __restrict__ x, float* __restrict__ out, int writeX)
{
    extern __shared__ float sm[];
    float* Ast = sm;              // [128][68]  p123 tile transposed
    float* Bst = sm + 128 * 68;   // [128][68]  w4 tile transposed

    const int tid = threadIdx.x;
    const int tx  = tid & 15;
    const int ty  = tid >> 4;
    const int n0  = blockIdx.x * 64;
    const int m0  = blockIdx.y * 64;

    for (int idx = tid; idx < 64 * 128; idx += 256) {
        int i = idx >> 7;
        int c = idx & 127;
        Ast[c * 68 + i] = g_po[(m0 + i) * 128 + c];
        Bst[c * 68 + i] = w4[(n0 + i) * 128 + c];
    }
    __syncthreads();

    float acc[4][4];
#pragma unroll
    for (int r = 0; r < 4; r++)
#pragma unroll
        for (int c = 0; c < 4; c++) acc[r][c] = 0.f;

#pragma unroll 4
    for (int c = 0; c < 128; c++) {
        float4 a = *(const float4*)&Ast[c * 68 + ty * 4];
        float4 b = *(const float4*)&Bst[c * 68 + tx * 4];
        acc[0][0] += a.x * b.x; acc[0][1] += a.x * b.y; acc[0][2] += a.x * b.z; acc[0][3] += a.x * b.w;
        acc[1][0] += a.y * b.x; acc[1][1] += a.y * b.y; acc[1][2] += a.y * b.z; acc[1][3] += a.y * b.w;
        acc[2][0] += a.z * b.x; acc[2][1] += a.z * b.y; acc[2][2] += a.z * b.z; acc[2][3] += a.z * b.w;
        acc[3][0] += a.w * b.x; acc[3][1] += a.w * b.y; acc[3][2] += a.w * b.z; acc[3][3] += a.w * b.w;
    }

#pragma unroll
    for (int ri = 0; ri < 4; ri++) {
        int r = m0 + ty * 4 + ri;
#pragma unroll
        for (int ci = 0; ci < 4; ci++) {
            int   oc = n0 + tx * 4 + ci;
            float v  = fmaxf(acc[ri][ci] + b4[oc], 0.f);
            int   t  = r * 256 + oc;
            float xv = x[t];
            out[t] = v + xv;
            if (writeX) out[NXE + t] = xv;
        }
    }
}

// ---------------------------------------------------------------------------
extern "C" void kernel_launch(void* const* d_in, const int* in_sizes, int n_in,
                              void* d_out, int out_size)
{
    const float* x  = (const float*)d_in[0];
    const float* w1 = (const float*)d_in[1];
    const float* b1 = (const float*)d_in[2];
    const float* w2 = (const float*)d_in[3];
    const float* b2 = (const float*)d_in[4];
    const float* w3 = (const float*)d_in[5];
    const float* b3 = (const float*)d_in[6];
    const float* w4 = (const float*)d_in[7];
    const float* b4 = (const float*)d_in[8];
    float* out = (float*)d_out;

    const int flash_smem = (128 * 68 + 128 * 64 + 64 * 128 + 64 * 64) * 4;  // 116736
    const int lin_smem   = 2 * 128 * 68 * 4;                                 // 69632
    cudaFuncSetAttribute(k_flash,  cudaFuncAttributeMaxDynamicSharedMemorySize, flash_smem);
    cudaFuncSetAttribute(k_linear, cudaFuncAttributeMaxDynamicSharedMemorySize, lin_smem);

    k_conv1 <<<dim3(4, 16, 4), 256>>>(x, w1, b1);
    k_conv23<<<dim3(2,  8, 8), 256>>>(x, w2, b2, w3, b3);
    k_flash <<<256, 256, flash_smem>>>();
    int writeX = (out_size >= 2 * NXE) ? 1 : 0;
    k_linear<<<dim3(4, 256), 256, lin_smem>>>(w4, b4, x, out, writeX);
}

// round 3
// speedup vs baseline: 2.6107x; 2.6107x over previous
#include <cuda_runtime.h>
#include <math.h>
#include <stdint.h>

// ---------------------------------------------------------------------------
// Shapes:
//   x  : (256,128,128) fp32
//   p1 = conv1(x)     -> g_p1 flat == Q  (16384,128) row-major (tf32-rounded)
//   p2 = conv2(x_ds)  -> g_p2 flat == K' (128,4096)  row-major (tf32-rounded)
//   p3 = conv3(x_ds)  -> g_p3 flat == V  (4096,128)  row-major (tf32-rounded)
//   attn = softmax(Q @ K' / 128); p123 = attn @ V   (mma.sync tf32, fused)
//   p4 = relu(p123 @ w4^T + b4) -> M = p4.reshape + x ; out = (M, x)
// ---------------------------------------------------------------------------

#define HP 128
#define WP 128
#define S1 16384
#define S2 4096
#define NXE 4194304

__device__ float g_p1[128 * S1];
__device__ float g_p2[128 * S2];
__device__ float g_p3[128 * S2];
__device__ float g_po[S1 * 128];   // p123

// ============================ helpers ======================================
__device__ __forceinline__ uint32_t smem_u32(const void* p) {
    uint32_t a;
    asm("{ .reg .u64 t; cvta.to.shared.u64 t, %1; cvt.u32.u64 %0, t; }"
        : "=r"(a) : "l"(p));
    return a;
}
__device__ __forceinline__ float rtf32(float x) {   // round-to-nearest tf32
    uint32_t u;
    asm("cvt.rna.tf32.f32 %0, %1;" : "=r"(u) : "f"(x));
    return __uint_as_float(u);
}
__device__ __forceinline__ void cpa16(uint32_t dst, const void* src) {
    uint64_t g = __cvta_generic_to_global(src);
    asm volatile("cp.async.cg.shared.global [%0], [%1], 16;" :: "r"(dst), "l"(g));
}
#define CP_COMMIT() asm volatile("cp.async.commit_group;")
#define CP_WAIT0()  asm volatile("cp.async.wait_group 0;" ::: "memory")

// m16n8k8 tf32 mma: D += A @ B  (A row-major m16k8, B col-major k8n8)
__device__ __forceinline__ void mma_tf32(
    float& d0, float& d1, float& d2, float& d3,
    uint32_t a0, uint32_t a1, uint32_t a2, uint32_t a3,
    uint32_t b0, uint32_t b1)
{
    asm volatile(
        "mma.sync.aligned.m16n8k8.row.col.f32.tf32.tf32.f32 "
        "{%0,%1,%2,%3}, {%4,%5,%6,%7}, {%8,%9}, {%0,%1,%2,%3};"
        : "+f"(d0), "+f"(d1), "+f"(d2), "+f"(d3)
        : "r"(a0), "r"(a1), "r"(a2), "r"(a3), "r"(b0), "r"(b1));
}

// ============================ convs ========================================
#define CIT 8
#define COT 32

template <int HL, int STRIDE>
__device__ __forceinline__ void conv_body(
    const float* __restrict__ x, const float* __restrict__ w,
    const float* __restrict__ bias, float* __restrict__ out,
    int h0, int w0, int co0)
{
    __shared__ float sin_[CIT][10][34];
    __shared__ float sw_[CIT][9][COT];

    const int tid = threadIdx.x;
    const int cog = tid >> 5;
    const int seg = tid & 31;
    const int row = seg >> 2;
    const int cb  = (seg & 3) << 3;

    float acc[4][8];
#pragma unroll
    for (int q = 0; q < 4; q++)
#pragma unroll
        for (int p = 0; p < 8; p++) acc[q][p] = 0.f;

    for (int cib = 0; cib < 256; cib += CIT) {
        __syncthreads();
        for (int idx = tid; idx < CIT * 10 * 34; idx += 256) {
            int ci  = idx / 340;
            int rem = idx - ci * 340;
            int r   = rem / 34;
            int c   = rem - r * 34;
            int gh  = h0 + r - 1;
            int gw  = w0 + c - 1;
            float v = 0.f;
            if ((unsigned)gh < (unsigned)HL && (unsigned)gw < (unsigned)HL)
                v = x[(cib + ci) * (HP * WP) + (gh * STRIDE) * WP + gw * STRIDE];
            sin_[ci][r][c] = v;
        }
        for (int idx = tid; idx < CIT * 9 * COT; idx += 256) {
            int co  = idx & (COT - 1);
            int t2  = idx >> 5;
            int tap = t2 % 9;
            int ci  = t2 / 9;
            sw_[ci][tap][co] = w[(co0 + co) * (256 * 9) + (cib + ci) * 9 + tap];
        }
        __syncthreads();

#pragma unroll 1
        for (int ci = 0; ci < CIT; ci++) {
            float4 wv[9];
#pragma unroll
            for (int t = 0; t < 9; t++)
                wv[t] = *(const float4*)&sw_[ci][t][cog * 4];
            float xin[3][10];
#pragma unroll
            for (int dy = 0; dy < 3; dy++)
#pragma unroll
                for (int c = 0; c < 10; c++)
                    xin[dy][c] = sin_[ci][row + dy][cb + c];
#pragma unroll
            for (int p = 0; p < 8; p++) {
#pragma unroll
                for (int dy = 0; dy < 3; dy++) {
#pragma unroll
                    for (int dx = 0; dx < 3; dx++) {
                        float  v  = xin[dy][p + dx];
                        float4 ww = wv[dy * 3 + dx];
                        acc[0][p] += ww.x * v;
                        acc[1][p] += ww.y * v;
                        acc[2][p] += ww.z * v;
                        acc[3][p] += ww.w * v;
                    }
                }
            }
        }
    }

#pragma unroll
    for (int q = 0; q < 4; q++) {
        int   co = co0 + cog * 4 + q;
        float bb = bias[co];
#pragma unroll
        for (int p = 0; p < 8; p++) {
            float v = fmaxf(acc[q][p] + bb, 0.f);
            out[co * (HL * HL) + (h0 + row) * HL + (w0 + cb + p)] = rtf32(v);
        }
    }
}

__global__ __launch_bounds__(256, 2)
void k_conv1(const float* __restrict__ x, const float* __restrict__ w1,
             const float* __restrict__ b1)
{
    conv_body<128, 1>(x, w1, b1, g_p1,
                      blockIdx.y * 8, blockIdx.x * 32, blockIdx.z * COT);
}

__global__ __launch_bounds__(256, 2)
void k_conv23(const float* __restrict__ x,
              const float* __restrict__ w2, const float* __restrict__ b2,
              const float* __restrict__ w3, const float* __restrict__ b3)
{
    int z   = blockIdx.z;
    int ws  = z >> 2;
    int co0 = (z & 3) * COT;
    const float* w  = ws ? w3 : w2;
    const float* bb = ws ? b3 : b2;
    float*       o  = ws ? g_p3 : g_p2;
    conv_body<64, 2>(x, w, bb, o, blockIdx.y * 8, blockIdx.x * 32, co0);
}

// ============================ mma.sync attention ===========================
// SMEM map (bytes):
//   P   [128][68]f         @ 0        34816   (stride 68:  A-frag conflict-free)
//   K0/K1 [128][72]f       @ 34816    2x36864 (stride 72 ≡ 8 mod 32: B conflict-free)
//   V0/V1 [64][136]f       @ 108544   2x34816 (stride 136 ≡ 8 mod 32)
#define PS_BYTES 34816
#define KB_BYTES 36864
#define VB_BYTES 34816
#define KS_OFF   PS_BYTES
#define VS_OFF   (PS_BYTES + 2 * KB_BYTES)
#define SMEM_FL  (PS_BYTES + 2 * KB_BYTES + 2 * VB_BYTES)   // 178176

__global__ __launch_bounds__(256, 1) void k_flash3()
{
    extern __shared__ char smc[];
    float*         smf = (float*)smc;
    const uint32_t sb  = smem_u32(smc);

    const int tid  = threadIdx.x;
    const int w    = tid >> 5;
    const int lane = tid & 31;
    const int g    = lane >> 2;     // group id (row within 8)
    const int tq   = lane & 3;      // thread-in-group
    const int row0 = blockIdx.x * 128;
    const int r0   = w * 16 + g;    // this thread's P/A row (block-local)

    // ---- Q A-fragments, held in registers for the whole KV loop ----
    uint32_t qa[16][4];
    {
        const float* q0 = g_p1 + (size_t)(row0 + w * 16 + g) * 128;
        const float* q1 = q0 + 8 * 128;
#pragma unroll
        for (int ks = 0; ks < 16; ++ks) {
            qa[ks][0] = __float_as_uint(__ldg(&q0[ks * 8 + tq]));
            qa[ks][1] = __float_as_uint(__ldg(&q1[ks * 8 + tq]));
            qa[ks][2] = __float_as_uint(__ldg(&q0[ks * 8 + tq + 4]));
            qa[ks][3] = __float_as_uint(__ldg(&q1[ks * 8 + tq + 4]));
        }
    }

    float oa[16][4];
#pragma unroll
    for (int nt = 0; nt < 16; ++nt)
#pragma unroll
        for (int i = 0; i < 4; ++i) oa[nt][i] = 0.f;
    float lA = 0.f, lB = 0.f;

    // ---- prefetch KV tile 0 ----
    for (int i = tid; i < 2048; i += 256) {
        int j = i >> 4, c = (i & 15) << 2;
        cpa16(sb + KS_OFF + (uint32_t)(j * 72 + c) * 4, &g_p2[(size_t)j * S2 + c]);
    }
    for (int i = tid; i < 2048; i += 256) {
        int r = i >> 5, c = (i & 31) << 2;
        cpa16(sb + VS_OFF + (uint32_t)(r * 136 + c) * 4, &g_p3[(size_t)r * 128 + c]);
    }
    CP_COMMIT();

    const float invtau = 1.0f / 128.0f;

    for (int kt = 0; kt < 64; ++kt) {
        const int buf = kt & 1;
        CP_WAIT0();
        __syncthreads();   // tile kt ready; all warps done with buf^1 (iter kt-1)

        if (kt + 1 < 64) {
            const int      kb = (kt + 1) * 64;
            const uint32_t kd = sb + KS_OFF + (uint32_t)(buf ^ 1) * KB_BYTES;
            const uint32_t vd = sb + VS_OFF + (uint32_t)(buf ^ 1) * VB_BYTES;
            for (int i = tid; i < 2048; i += 256) {
                int j = i >> 4, c = (i & 15) << 2;
                cpa16(kd + (uint32_t)(j * 72 + c) * 4,
                      &g_p2[(size_t)j * S2 + kb + c]);
            }
            for (int i = tid; i < 2048; i += 256) {
                int r = i >> 5, c = (i & 31) << 2;
                cpa16(vd + (uint32_t)(r * 136 + c) * 4,
                      &g_p3[(size_t)(kb + r) * 128 + c]);
            }
            CP_COMMIT();
        }

        // ---- GEMM1: S(16x64 per warp) = Qw(16x128) @ K'(128x64) ----
        const float* Kb = smf + (KS_OFF + buf * KB_BYTES) / 4;
        float s[8][4];
#pragma unroll
        for (int nt = 0; nt < 8; ++nt)
#pragma unroll
            for (int i = 0; i < 4; ++i) s[nt][i] = 0.f;

#pragma unroll
        for (int ks = 0; ks < 16; ++ks) {
            const int kr = ks * 8 + tq;
#pragma unroll
            for (int nt = 0; nt < 8; ++nt) {
                uint32_t b0 = __float_as_uint(Kb[kr * 72 + nt * 8 + g]);
                uint32_t b1 = __float_as_uint(Kb[(kr + 4) * 72 + nt * 8 + g]);
                mma_tf32(s[nt][0], s[nt][1], s[nt][2], s[nt][3],
                         qa[ks][0], qa[ks][1], qa[ks][2], qa[ks][3], b0, b1);
            }
        }

        // ---- softmax numerator (shift-free: |S|/128 small, exp can't
        //      overflow; softmax is shift-invariant so result is exact) ----
        float* Pw = smf;   // stride 68, warp-private rows [w*16, w*16+16)
#pragma unroll
        for (int nt = 0; nt < 8; ++nt) {
            float p0 = rtf32(__expf(s[nt][0] * invtau));
            float p1 = rtf32(__expf(s[nt][1] * invtau));
            float p2 = rtf32(__expf(s[nt][2] * invtau));
            float p3 = rtf32(__expf(s[nt][3] * invtau));
            lA += p0 + p1;
            lB += p2 + p3;
            *(float2*)&Pw[r0 * 68 + nt * 8 + 2 * tq]       = make_float2(p0, p1);
            *(float2*)&Pw[(r0 + 8) * 68 + nt * 8 + 2 * tq] = make_float2(p2, p3);
        }
        __syncwarp();

        // ---- GEMM2: O(16x128 per warp) += P(16x64) @ V(64x128) ----
        const float* Vb = smf + (VS_OFF + buf * VB_BYTES) / 4;
#pragma unroll
        for (int ks = 0; ks < 8; ++ks) {
            uint32_t a0 = __float_as_uint(Pw[r0 * 68 + ks * 8 + tq]);
            uint32_t a1 = __float_as_uint(Pw[(r0 + 8) * 68 + ks * 8 + tq]);
            uint32_t a2 = __float_as_uint(Pw[r0 * 68 + ks * 8 + tq + 4]);
            uint32_t a3 = __float_as_uint(Pw[(r0 + 8) * 68 + ks * 8 + tq + 4]);
            const int kr = ks * 8 + tq;
#pragma unroll
            for (int nt = 0; nt < 16; ++nt) {
                uint32_t b0 = __float_as_uint(Vb[kr * 136 + nt * 8 + g]);
                uint32_t b1 = __float_as_uint(Vb[(kr + 4) * 136 + nt * 8 + g]);
                mma_tf32(oa[nt][0], oa[nt][1], oa[nt][2], oa[nt][3],
                         a0, a1, a2, a3, b0, b1);
            }
        }
        __syncwarp();   // P reuse next iter is warp-local
    }

    // ---- normalize by row sums and store ----
    lA += __shfl_xor_sync(0xffffffffu, lA, 1);
    lA += __shfl_xor_sync(0xffffffffu, lA, 2);
    lB += __shfl_xor_sync(0xffffffffu, lB, 1);
    lB += __shfl_xor_sync(0xffffffffu, lB, 2);
    const float iA = 1.0f / lA;
    const float iB = 1.0f / lB;

    float* po  = g_po + (size_t)(row0 + w * 16 + g) * 128;
    float* po8 = po + 8 * 128;
#pragma unroll
    for (int nt = 0; nt < 16; ++nt) {
        *(float2*)&po[nt * 8 + 2 * tq]  = make_float2(oa[nt][0] * iA, oa[nt][1] * iA);
        *(float2*)&po8[nt * 8 + 2 * tq] = make_float2(oa[nt][2] * iB, oa[nt][3] * iB);
    }
}

// ============================ linear =======================================
__global__ __launch_bounds__(256)
void k_linear(const float* __restrict__ w4, const float* __restrict__ b4,
              const float* __restrict__ x, float* __restrict__ out, int writeX)
{
    extern __shared__ float smf[];
    float* Ast = smf;
    float* Bst = smf + 128 * 68;

    const int tid = threadIdx.x;
    const int tx  = tid & 15;
    const int ty  = tid >> 4;
    const int n0  = blockIdx.x * 64;
    const int m0  = blockIdx.y * 64;

    for (int idx = tid; idx < 64 * 128; idx += 256) {
        int i = idx >> 7;
        int c = idx & 127;
        Ast[c * 68 + i] = g_po[(m0 + i) * 128 + c];
        Bst[c * 68 + i] = w4[(n0 + i) * 128 + c];
    }
    __syncthreads();

    float acc[4][4];
#pragma unroll
    for (int r = 0; r < 4; r++)
#pragma unroll
        for (int c = 0; c < 4; c++) acc[r][c] = 0.f;

#pragma unroll 4
    for (int c = 0; c < 128; c++) {
        float4 a = *(const float4*)&Ast[c * 68 + ty * 4];
        float4 b = *(const float4*)&Bst[c * 68 + tx * 4];
        acc[0][0] += a.x * b.x; acc[0][1] += a.x * b.y; acc[0][2] += a.x * b.z; acc[0][3] += a.x * b.w;
        acc[1][0] += a.y * b.x; acc[1][1] += a.y * b.y; acc[1][2] += a.y * b.z; acc[1][3] += a.y * b.w;
        acc[2][0] += a.z * b.x; acc[2][1] += a.z * b.y; acc[2][2] += a.z * b.z; acc[2][3] += a.z * b.w;
        acc[3][0] += a.w * b.x; acc[3][1] += a.w * b.y; acc[3][2] += a.w * b.z; acc[3][3] += a.w * b.w;
    }

#pragma unroll
    for (int ri = 0; ri < 4; ri++) {
        int r = m0 + ty * 4 + ri;
#pragma unroll
        for (int ci = 0; ci < 4; ci++) {
            int   oc = n0 + tx * 4 + ci;
            float v  = fmaxf(acc[ri][ci] + b4[oc], 0.f);
            int   t  = r * 256 + oc;
            float xv = x[t];
            out[t] = v + xv;
            if (writeX) out[NXE + t] = xv;
        }
    }
}

// ===========================================================================
extern "C" void kernel_launch(void* const* d_in, const int* in_sizes, int n_in,
                              void* d_out, int out_size)
{
    const float* x  = (const float*)d_in[0];
    const float* w1 = (const float*)d_in[1];
    const float* b1 = (const float*)d_in[2];
    const float* w2 = (const float*)d_in[3];
    const float* b2 = (const float*)d_in[4];
    const float* w3 = (const float*)d_in[5];
    const float* b3 = (const float*)d_in[6];
    const float* w4 = (const float*)d_in[7];
    const float* b4 = (const float*)d_in[8];
    float* out = (float*)d_out;

    const int lin_smem = 2 * 128 * 68 * 4;
    cudaFuncSetAttribute(k_flash3, cudaFuncAttributeMaxDynamicSharedMemorySize, SMEM_FL);
    cudaFuncSetAttribute(k_linear, cudaFuncAttributeMaxDynamicSharedMemorySize, lin_smem);

    k_conv1 <<<dim3(4, 16, 4), 256>>>(x, w1, b1);
    k_conv23<<<dim3(2,  8, 8), 256>>>(x, w2, b2, w3, b3);
    k_flash3<<<128, 256, SMEM_FL>>>();
    int writeX = (out_size >= 2 * NXE) ? 1 : 0;
    k_linear<<<dim3(4, 256), 256, lin_smem>>>(w4, b4, x, out, writeX);
}

// round 4
// speedup vs baseline: 4.8448x; 1.8557x over previous
#include <cuda_runtime.h>
#include <math.h>
#include <stdint.h>

// ---------------------------------------------------------------------------
//   x  : (256,128,128) fp32
//   p1 = conv1(x)     -> g_p1 flat == Q  (16384,128) row-major (tf32-rounded)
//   p2 = conv2(x_ds)  -> g_p2 flat == K' (128,4096)  row-major (tf32-rounded)
//   p3 = conv3(x_ds)  -> g_p3 flat == V  (4096,128)  row-major (tf32-rounded)
//   attn = softmax(Q @ K' / 128); p123 = attn @ V   (mma.sync tf32, fused)
//   p4 = relu(p123 @ w4^T + b4) -> M = p4.reshape + x ; out = (M, x)
//   Convs are implicit-GEMM on tf32 mma.sync (M=co, N=px, K=ci*9=2304).
// ---------------------------------------------------------------------------

#define HP 128
#define WP 128
#define S1 16384
#define S2 4096
#define NXE 4194304

__device__ float g_p1[128 * S1];
__device__ float g_p2[128 * S2];
__device__ float g_p3[128 * S2];
__device__ float g_po[S1 * 128];     // p123
__device__ float g_wt1[128 * 2304];  // weights re-laid-out [co][chunk][tap][ci]
__device__ float g_wt2[128 * 2304];
__device__ float g_wt3[128 * 2304];

// ============================ helpers ======================================
__device__ __forceinline__ uint32_t smem_u32(const void* p) {
    uint32_t a;
    asm("{ .reg .u64 t; cvta.to.shared.u64 t, %1; cvt.u32.u64 %0, t; }"
        : "=r"(a) : "l"(p));
    return a;
}
__device__ __forceinline__ float rtf32(float x) {
    uint32_t u;
    asm("cvt.rna.tf32.f32 %0, %1;" : "=r"(u) : "f"(x));
    return __uint_as_float(u);
}
__device__ __forceinline__ void cpa16(uint32_t dst, const void* src) {
    uint64_t g = __cvta_generic_to_global(src);
    asm volatile("cp.async.cg.shared.global [%0], [%1], 16;" :: "r"(dst), "l"(g));
}
#define CP_COMMIT() asm volatile("cp.async.commit_group;")
#define CP_WAIT0()  asm volatile("cp.async.wait_group 0;" ::: "memory")
#define CP_WAIT1()  asm volatile("cp.async.wait_group 1;" ::: "memory")

// m16n8k8 tf32 mma: D += A @ B
__device__ __forceinline__ void mma_tf32(
    float& d0, float& d1, float& d2, float& d3,
    uint32_t a0, uint32_t a1, uint32_t a2, uint32_t a3,
    uint32_t b0, uint32_t b1)
{
    asm volatile(
        "mma.sync.aligned.m16n8k8.row.col.f32.tf32.tf32.f32 "
        "{%0,%1,%2,%3}, {%4,%5,%6,%7}, {%8,%9}, {%0,%1,%2,%3};"
        : "+f"(d0), "+f"(d1), "+f"(d2), "+f"(d3)
        : "r"(a0), "r"(a1), "r"(a2), "r"(a3), "r"(b0), "r"(b1));
}

// ============================ weight prep ==================================
// wt[co][chunk][tap][ci'] = rtf32(w[co][chunk*8+ci'][tap]);  K chunk = 72
__global__ void k_prepw(const float* __restrict__ w1,
                        const float* __restrict__ w2,
                        const float* __restrict__ w3)
{
    int i = blockIdx.x * 256 + threadIdx.x;
    if (i >= 128 * 2304) return;
    int co = i / 2304, r = i - co * 2304;
    int chunk = r / 72, q = r - chunk * 72;
    int tap = q >> 3, ci = q & 7;
    int src = co * 2304 + (chunk * 8 + ci) * 9 + tap;
    g_wt1[i] = rtf32(w1[src]);
    g_wt2[i] = rtf32(w2[src]);
    g_wt3[i] = rtf32(w3[src]);
}

// ============================ conv1 (tf32 implicit GEMM) ===================
// CTA = one image row h: out 128co x 128px, K = 2304 in 32 chunks of 72.
// smem: Aw[2][128][76] (stride 76 -> conflict-free A frags),
//       Xs[2][8ci][3dy][136] (stride 408 -> conflict-free B frags; pad L4/R4)
#define AW1 (128 * 76)          // 9728 floats / buffer
#define XS1 (8 * 3 * 136)       // 3264 floats / buffer
#define C1_SMEM ((2 * AW1 + 2 * XS1) * 4)   // 103936 B

__global__ __launch_bounds__(256, 1)
void k_conv1t(const float* __restrict__ x, const float* __restrict__ b1)
{
    extern __shared__ float sf[];
    float*         Aw = sf;
    float*         Xs = sf + 2 * AW1;
    const uint32_t sb = smem_u32(sf);
    const uint32_t xb = sb + 2 * AW1 * 4;

    const int tid = threadIdx.x;
    const int w   = tid >> 5;
    const int g   = (tid & 31) >> 2;
    const int tq  = tid & 3;
    const int h   = blockIdx.x;

    for (int i = tid; i < 2 * XS1; i += 256) Xs[i] = 0.f;
    __syncthreads();

    // stage(chunk c -> buffer b)
    auto stage = [&](int c, int b) {
        const float* wsrc = g_wt1 + (size_t)c * 72;
        uint32_t     aw   = sb + (uint32_t)b * (AW1 * 4);
        for (int i = tid; i < 2304; i += 256) {          // 9/thread
            int co = i / 18, j = i - co * 18;
            cpa16(aw + (uint32_t)(co * 76 + j * 4) * 4,
                  wsrc + (size_t)co * 2304 + j * 4);
        }
        uint32_t     xw   = xb + (uint32_t)b * (XS1 * 4);
        const float* xsrc = x + (size_t)(c * 8) * 16384;
        for (int i = tid; i < 768; i += 256) {           // 3/thread
            int row = i >> 5, j = i & 31;
            int ci = row / 3, dy = row - ci * 3;
            int hh = h + dy - 1;
            if ((unsigned)hh < 128u)
                cpa16(xw + (uint32_t)(ci * 408 + dy * 136 + 4 + j * 4) * 4,
                      xsrc + (size_t)ci * 16384 + hh * 128 + j * 4);
        }
    };

    stage(0, 0);
    CP_COMMIT();

    float acc[16][4];
#pragma unroll
    for (int nt = 0; nt < 16; ++nt)
#pragma unroll
        for (int i = 0; i < 4; ++i) acc[nt][i] = 0.f;

    for (int c = 0; c < 32; ++c) {
        const int buf = c & 1;
        if (c + 1 < 32) { stage(c + 1, buf ^ 1); CP_COMMIT(); CP_WAIT1(); }
        else            { CP_WAIT0(); }
        __syncthreads();

        const float* A  = Aw + buf * AW1 + (w * 16 + g) * 76;
        const float* X0 = Xs + buf * XS1 + tq * 408 + 3 + g;
        const float* X4 = X0 + 4 * 408;

#pragma unroll
        for (int ks = 0; ks < 9; ++ks) {
            const int dy = ks / 3, dx = ks - dy * 3;
            uint32_t a0 = __float_as_uint(A[ks * 8 + tq]);
            uint32_t a1 = __float_as_uint(A[8 * 76 + ks * 8 + tq]);
            uint32_t a2 = __float_as_uint(A[ks * 8 + tq + 4]);
            uint32_t a3 = __float_as_uint(A[8 * 76 + ks * 8 + tq + 4]);
            const float* xr0 = X0 + dy * 136 + dx;
            const float* xr4 = X4 + dy * 136 + dx;
#pragma unroll
            for (int nt = 0; nt < 16; ++nt) {
                uint32_t b0 = __float_as_uint(xr0[nt * 8]);
                uint32_t b1 = __float_as_uint(xr4[nt * 8]);
                mma_tf32(acc[nt][0], acc[nt][1], acc[nt][2], acc[nt][3],
                         a0, a1, a2, a3, b0, b1);
            }
        }
        __syncthreads();
    }

    const int   co0 = w * 16 + g;
    const float bb0 = b1[co0], bb1 = b1[co0 + 8];
#pragma unroll
    for (int nt = 0; nt < 16; ++nt) {
        int px = h * 128 + nt * 8 + 2 * tq;
        float2 v0 = make_float2(rtf32(fmaxf(acc[nt][0] + bb0, 0.f)),
                                rtf32(fmaxf(acc[nt][1] + bb0, 0.f)));
        float2 v1 = make_float2(rtf32(fmaxf(acc[nt][2] + bb1, 0.f)),
                                rtf32(fmaxf(acc[nt][3] + bb1, 0.f)));
        *(float2*)&g_p1[(size_t)co0 * 16384 + px]       = v0;
        *(float2*)&g_p1[(size_t)(co0 + 8) * 16384 + px] = v1;
    }
}

// ============================ conv2/3 (tf32 implicit GEMM, stride 2) =======
// CTA = one output row hp (64 px) of conv2 (by=0) or conv3 (by=1).
// smem: Aw[2][128][76], Xs[2][8ci][3][72] (stride 216; pad L1)
#define XS2 (8 * 3 * 72)        // 1728 floats / buffer
#define C23_SMEM ((2 * AW1 + 2 * XS2) * 4)   // 91648 B

__global__ __launch_bounds__(256, 1)
void k_conv23t(const float* __restrict__ x,
               const float* __restrict__ b2, const float* __restrict__ b3)
{
    extern __shared__ float sf[];
    float*         Aw = sf;
    float*         Xs = sf + 2 * AW1;
    const uint32_t sb = smem_u32(sf);

    const int    sel  = blockIdx.y;
    const float* wsel = sel ? g_wt3 : g_wt2;
    const float* bsel = sel ? b3 : b2;
    float*       osel = sel ? g_p3 : g_p2;

    const int tid = threadIdx.x;
    const int w   = tid >> 5;
    const int g   = (tid & 31) >> 2;
    const int tq  = tid & 3;
    const int hp  = blockIdx.x;

    for (int i = tid; i < 2 * XS2; i += 256) Xs[i] = 0.f;
    __syncthreads();

    auto stage_aw = [&](int c, int b) {
        const float* wsrc = wsel + (size_t)c * 72;
        uint32_t     aw   = sb + (uint32_t)b * (AW1 * 4);
        for (int i = tid; i < 2304; i += 256) {
            int co = i / 18, j = i - co * 18;
            cpa16(aw + (uint32_t)(co * 76 + j * 4) * 4,
                  wsrc + (size_t)co * 2304 + j * 4);
        }
    };
    // x_ds gather (stride-2) via register prefetch: 1536 elems = 6/thread
    float pre[6];
    auto ldg_xs = [&](int c) {
#pragma unroll
        for (int q = 0; q < 6; ++q) {
            int i   = q * 256 + tid;
            int ci  = i / 192, rem = i - ci * 192;
            int r   = rem >> 6, col = rem & 63;
            int a   = hp + r - 1;
            pre[q]  = ((unsigned)a < 64u)
                      ? x[(size_t)(c * 8 + ci) * 16384 + (2 * a) * 128 + 2 * col]
                      : 0.f;
        }
    };
    auto sts_xs = [&](int b) {
#pragma unroll
        for (int q = 0; q < 6; ++q) {
            int i  = q * 256 + tid;
            int ci = i / 192, rem = i - ci * 192;
            int r  = rem >> 6, col = rem & 63;
            Xs[b * XS2 + ci * 216 + r * 72 + 1 + col] = pre[q];
        }
    };

    stage_aw(0, 0);
    CP_COMMIT();
    ldg_xs(0);

    float acc[8][4];
#pragma unroll
    for (int nt = 0; nt < 8; ++nt)
#pragma unroll
        for (int i = 0; i < 4; ++i) acc[nt][i] = 0.f;

    for (int c = 0; c < 32; ++c) {
        const int buf = c & 1;
        sts_xs(buf);                       // chunk c rows -> buf
        if (c + 1 < 32) {
            stage_aw(c + 1, buf ^ 1);
            CP_COMMIT();
            ldg_xs(c + 1);
            CP_WAIT1();
        } else {
            CP_WAIT0();
        }
        __syncthreads();

        const float* A  = Aw + buf * AW1 + (w * 16 + g) * 76;
        const float* X0 = Xs + buf * XS2 + tq * 216 + g;
        const float* X4 = X0 + 4 * 216;

#pragma unroll
        for (int ks = 0; ks < 9; ++ks) {
            const int dy = ks / 3, dx = ks - dy * 3;
            uint32_t a0 = __float_as_uint(A[ks * 8 + tq]);
            uint32_t a1 = __float_as_uint(A[8 * 76 + ks * 8 + tq]);
            uint32_t a2 = __float_as_uint(A[ks * 8 + tq + 4]);
            uint32_t a3 = __float_as_uint(A[8 * 76 + ks * 8 + tq + 4]);
            const float* xr0 = X0 + dy * 72 + dx;
            const float* xr4 = X4 + dy * 72 + dx;
#pragma unroll
            for (int nt = 0; nt < 8; ++nt) {
                uint32_t b0 = __float_as_uint(xr0[nt * 8]);
                uint32_t b1 = __float_as_uint(xr4[nt * 8]);
                mma_tf32(acc[nt][0], acc[nt][1], acc[nt][2], acc[nt][3],
                         a0, a1, a2, a3, b0, b1);
            }
        }
        __syncthreads();
    }

    const int   co0 = w * 16 + g;
    const float bb0 = bsel[co0], bb1 = bsel[co0 + 8];
#pragma unroll
    for (int nt = 0; nt < 8; ++nt) {
        int px = hp * 64 + nt * 8 + 2 * tq;
        float2 v0 = make_float2(rtf32(fmaxf(acc[nt][0] + bb0, 0.f)),
                                rtf32(fmaxf(acc[nt][1] + bb0, 0.f)));
        float2 v1 = make_float2(rtf32(fmaxf(acc[nt][2] + bb1, 0.f)),
                                rtf32(fmaxf(acc[nt][3] + bb1, 0.f)));
        *(float2*)&osel[(size_t)co0 * 4096 + px]       = v0;
        *(float2*)&osel[(size_t)(co0 + 8) * 4096 + px] = v1;
    }
}

// ============================ mma.sync attention ===========================
#define PS_BYTES 34816
#define KB_BYTES 36864
#define VB_BYTES 34816
#define KS_OFF   PS_BYTES
#define VS_OFF   (PS_BYTES + 2 * KB_BYTES)
#define SMEM_FL  (PS_BYTES + 2 * KB_BYTES + 2 * VB_BYTES)   // 178176

__global__ __launch_bounds__(256, 1) void k_flash3()
{
    extern __shared__ char smc[];
    float*         smf = (float*)smc;
    const uint32_t sb  = smem_u32(smc);

    const int tid  = threadIdx.x;
    const int w    = tid >> 5;
    const int lane = tid & 31;
    const int g    = lane >> 2;
    const int tq   = lane & 3;
    const int row0 = blockIdx.x * 128;
    const int r0   = w * 16 + g;

    uint32_t qa[16][4];
    {
        const float* q0 = g_p1 + (size_t)(row0 + w * 16 + g) * 128;
        const float* q1 = q0 + 8 * 128;
#pragma unroll
        for (int ks = 0; ks < 16; ++ks) {
            qa[ks][0] = __float_as_uint(__ldg(&q0[ks * 8 + tq]));
            qa[ks][1] = __float_as_uint(__ldg(&q1[ks * 8 + tq]));
            qa[ks][2] = __float_as_uint(__ldg(&q0[ks * 8 + tq + 4]));
            qa[ks][3] = __float_as_uint(__ldg(&q1[ks * 8 + tq + 4]));
        }
    }

    float oa[16][4];
#pragma unroll
    for (int nt = 0; nt < 16; ++nt)
#pragma unroll
        for (int i = 0; i < 4; ++i) oa[nt][i] = 0.f;
    float lA = 0.f, lB = 0.f;

    for (int i = tid; i < 2048; i += 256) {
        int j = i >> 4, c = (i & 15) << 2;
        cpa16(sb + KS_OFF + (uint32_t)(j * 72 + c) * 4, &g_p2[(size_t)j * S2 + c]);
    }
    for (int i = tid; i < 2048; i += 256) {
        int r = i >> 5, c = (i & 31) << 2;
        cpa16(sb + VS_OFF + (uint32_t)(r * 136 + c) * 4, &g_p3[(size_t)r * 128 + c]);
    }
    CP_COMMIT();

    const float invtau = 1.0f / 128.0f;

    for (int kt = 0; kt < 64; ++kt) {
        const int buf = kt & 1;
        CP_WAIT0();
        __syncthreads();

        if (kt + 1 < 64) {
            const int      kb = (kt + 1) * 64;
            const uint32_t kd = sb + KS_OFF + (uint32_t)(buf ^ 1) * KB_BYTES;
            const uint32_t vd = sb + VS_OFF + (uint32_t)(buf ^ 1) * VB_BYTES;
            for (int i = tid; i < 2048; i += 256) {
                int j = i >> 4, c = (i & 15) << 2;
                cpa16(kd + (uint32_t)(j * 72 + c) * 4,
                      &g_p2[(size_t)j * S2 + kb + c]);
            }
            for (int i = tid; i < 2048; i += 256) {
                int r = i >> 5, c = (i & 31) << 2;
                cpa16(vd + (uint32_t)(r * 136 + c) * 4,
                      &g_p3[(size_t)(kb + r) * 128 + c]);
            }
            CP_COMMIT();
        }

        const float* Kb = smf + (KS_OFF + buf * KB_BYTES) / 4;
        float s[8][4];
#pragma unroll
        for (int nt = 0; nt < 8; ++nt)
#pragma unroll
            for (int i = 0; i < 4; ++i) s[nt][i] = 0.f;

#pragma unroll
        for (int ks = 0; ks < 16; ++ks) {
            const int kr = ks * 8 + tq;
#pragma unroll
            for (int nt = 0; nt < 8; ++nt) {
                uint32_t b0 = __float_as_uint(Kb[kr * 72 + nt * 8 + g]);
                uint32_t b1 = __float_as_uint(Kb[(kr + 4) * 72 + nt * 8 + g]);
                mma_tf32(s[nt][0], s[nt][1], s[nt][2], s[nt][3],
                         qa[ks][0], qa[ks][1], qa[ks][2], qa[ks][3], b0, b1);
            }
        }

        float* Pw = smf;
#pragma unroll
        for (int nt = 0; nt < 8; ++nt) {
            float p0 = rtf32(__expf(s[nt][0] * invtau));
            float p1 = rtf32(__expf(s[nt][1] * invtau));
            float p2 = rtf32(__expf(s[nt][2] * invtau));
            float p3 = rtf32(__expf(s[nt][3] * invtau));
            lA += p0 + p1;
            lB += p2 + p3;
            *(float2*)&Pw[r0 * 68 + nt * 8 + 2 * tq]       = make_float2(p0, p1);
            *(float2*)&Pw[(r0 + 8) * 68 + nt * 8 + 2 * tq] = make_float2(p2, p3);
        }
        __syncwarp();

        const float* Vb = smf + (VS_OFF + buf * VB_BYTES) / 4;
#pragma unroll
        for (int ks = 0; ks < 8; ++ks) {
            uint32_t a0 = __float_as_uint(Pw[r0 * 68 + ks * 8 + tq]);
            uint32_t a1 = __float_as_uint(Pw[(r0 + 8) * 68 + ks * 8 + tq]);
            uint32_t a2 = __float_as_uint(Pw[r0 * 68 + ks * 8 + tq + 4]);
            uint32_t a3 = __float_as_uint(Pw[(r0 + 8) * 68 + ks * 8 + tq + 4]);
            const int kr = ks * 8 + tq;
#pragma unroll
            for (int nt = 0; nt < 16; ++nt) {
                uint32_t b0 = __float_as_uint(Vb[kr * 136 + nt * 8 + g]);
                uint32_t b1 = __float_as_uint(Vb[(kr + 4) * 136 + nt * 8 + g]);
                mma_tf32(oa[nt][0], oa[nt][1], oa[nt][2], oa[nt][3],
                         a0, a1, a2, a3, b0, b1);
            }
        }
        __syncwarp();
    }

    lA += __shfl_xor_sync(0xffffffffu, lA, 1);
    lA += __shfl_xor_sync(0xffffffffu, lA, 2);
    lB += __shfl_xor_sync(0xffffffffu, lB, 1);
    lB += __shfl_xor_sync(0xffffffffu, lB, 2);
    const float iA = 1.0f / lA;
    const float iB = 1.0f / lB;

    float* po  = g_po + (size_t)(row0 + w * 16 + g) * 128;
    float* po8 = po + 8 * 128;
#pragma unroll
    for (int nt = 0; nt < 16; ++nt) {
        *(float2*)&po[nt * 8 + 2 * tq]  = make_float2(oa[nt][0] * iA, oa[nt][1] * iA);
        *(float2*)&po8[nt * 8 + 2 * tq] = make_float2(oa[nt][2] * iB, oa[nt][3] * iB);
    }
}

// ============================ linear =======================================
__global__ __launch_bounds__(256)
void k_linear(const float* __restrict__ w4, const float* __restrict__ b4,
              const float* __restrict__ x, float* __restrict__ out, int writeX)
{
    extern __shared__ float smf[];
    float* Ast = smf;
    float* Bst = smf + 128 * 68;

    const int tid = threadIdx.x;
    const int tx  = tid & 15;
    const int ty  = tid >> 4;
    const int n0  = blockIdx.x * 64;
    const int m0  = blockIdx.y * 64;

    for (int idx = tid; idx < 64 * 128; idx += 256) {
        int i = idx >> 7;
        int c = idx & 127;
        Ast[c * 68 + i] = g_po[(m0 + i) * 128 + c];
        Bst[c * 68 + i] = w4[(n0 + i) * 128 + c];
    }
    __syncthreads();

    float acc[4][4];
#pragma unroll
    for (int r = 0; r < 4; r++)
#pragma unroll
        for (int c = 0; c < 4; c++) acc[r][c] = 0.f;

#pragma unroll 4
    for (int c = 0; c < 128; c++) {
        float4 a = *(const float4*)&Ast[c * 68 + ty * 4];
        float4 b = *(const float4*)&Bst[c * 68 + tx * 4];
        acc[0][0] += a.x * b.x; acc[0][1] += a.x * b.y; acc[0][2] += a.x * b.z; acc[0][3] += a.x * b.w;
        acc[1][0] += a.y * b.x; acc[1][1] += a.y * b.y; acc[1][2] += a.y * b.z; acc[1][3] += a.y * b.w;
        acc[2][0] += a.z * b.x; acc[2][1] += a.z * b.y; acc[2][2] += a.z * b.z; acc[2][3] += a.z * b.w;
        acc[3][0] += a.w * b.x; acc[3][1] += a.w * b.y; acc[3][2] += a.w * b.z; acc[3][3] += a.w * b.w;
    }

#pragma unroll
    for (int ri = 0; ri < 4; ri++) {
        int r = m0 + ty * 4 + ri;
#pragma unroll
        for (int ci = 0; ci < 4; ci++) {
            int   oc = n0 + tx * 4 + ci;
            float v  = fmaxf(acc[ri][ci] + b4[oc], 0.f);
            int   t  = r * 256 + oc;
            float xv = x[t];
            out[t] = v + xv;
            if (writeX) out[NXE + t] = xv;
        }
    }
}

// ===========================================================================
extern "C" void kernel_launch(void* const* d_in, const int* in_sizes, int n_in,
                              void* d_out, int out_size)
{
    const float* x  = (const float*)d_in[0];
    const float* w1 = (const float*)d_in[1];
    const float* b1 = (const float*)d_in[2];
    const float* w2 = (const float*)d_in[3];
    const float* b2 = (const float*)d_in[4];
    const float* w3 = (const float*)d_in[5];
    const float* b3 = (const float*)d_in[6];
    const float* w4 = (const float*)d_in[7];
    const float* b4 = (const float*)d_in[8];
    float* out = (float*)d_out;

    const int lin_smem = 2 * 128 * 68 * 4;
    cudaFuncSetAttribute(k_conv1t,  cudaFuncAttributeMaxDynamicSharedMemorySize, C1_SMEM);
    cudaFuncSetAttribute(k_conv23t, cudaFuncAttributeMaxDynamicSharedMemorySize, C23_SMEM);
    cudaFuncSetAttribute(k_flash3,  cudaFuncAttributeMaxDynamicSharedMemorySize, SMEM_FL);
    cudaFuncSetAttribute(k_linear,  cudaFuncAttributeMaxDynamicSharedMemorySize, lin_smem);

    k_prepw  <<<(128 * 2304 + 255) / 256, 256>>>(w1, w2, w3);
    k_conv1t <<<128, 256, C1_SMEM>>>(x, b1);
    k_conv23t<<<dim3(64, 2), 256, C23_SMEM>>>(x, b2, b3);
    k_flash3 <<<128, 256, SMEM_FL>>>();
    int writeX = (out_size >= 2 * NXE) ? 1 : 0;
    k_linear <<<dim3(4, 256), 256, lin_smem>>>(w4, b4, x, out, writeX);
}